// round 5
// baseline (speedup 1.0000x reference)
#include <cuda_runtime.h>
#include <mma.h>
#include <cstddef>
#include <cstdint>

using namespace nvcuda;

// Problem constants
#define BATCH 128
#define HH 14
#define WW 14
#define CC 768
#define NHEAD 12
#define HDIM 64
#define HWSZ 196          // 14*14
#define C3 2304           // 3*C
#define MROWS 25088       // BATCH*HWSZ
#define NHEADS_TOTAL 1536 // BATCH*NHEAD
#define GK 768            // K dim of both GEMMs

// Scratch buffers (device globals: no allocation allowed)
__device__ float g_qkv[(size_t)MROWS * C3];  // (B, HW, 3, NH, HD) fp32
__device__ float g_att[(size_t)MROWS * CC];  // attention out, tf32-rounded
__device__ float g_x[(size_t)MROWS * CC];    // x, tf32-rounded
__device__ float g_wqkv[(size_t)CC * C3];    // w_qkv, tf32-rounded
__device__ float g_wproj[(size_t)CC * CC];   // w_proj, tf32-rounded

// ---------------------------------------------------------------------------
// tf32 round helper + conversion kernel (fp32 -> tf32-RN stored as fp32)
// ---------------------------------------------------------------------------
__device__ __forceinline__ float f2tf32(float f) {
    uint32_t r;
    asm("cvt.rna.tf32.f32 %0, %1;" : "=r"(r) : "f"(f));
    return __uint_as_float(r);
}

__global__ void round_tf32_kernel(const float* __restrict__ in,
                                  float* __restrict__ out, int n4)
{
    int i = blockIdx.x * blockDim.x + threadIdx.x;
    if (i < n4) {
        float4 v = ((const float4*)in)[i];
        v.x = f2tf32(v.x); v.y = f2tf32(v.y);
        v.z = f2tf32(v.z); v.w = f2tf32(v.w);
        ((float4*)out)[i] = v;
    }
}

// ---------------------------------------------------------------------------
// cp.async helpers
// ---------------------------------------------------------------------------
__device__ __forceinline__ void cpa16(void* s, const void* g) {
    uint32_t sa = (uint32_t)__cvta_generic_to_shared(s);
    asm volatile("cp.async.cg.shared.global [%0], [%1], 16;\n" ::"r"(sa), "l"(g));
}
__device__ __forceinline__ void cpa_commit() {
    asm volatile("cp.async.commit_group;\n" ::);
}
template <int N>
__device__ __forceinline__ void cpa_wait() {
    asm volatile("cp.async.wait_group %0;\n" ::"n"(N));
}

// ---------------------------------------------------------------------------
// 3-stage pipelined tf32 GEMM, inputs pre-rounded to tf32 (no in-loop cvt).
// C = A(MxK) @ B(KxN) + bias.  BM=BN=128, BK=32, 256 threads (8 warps,
// 2x4 layout, 64x32 per warp), 2 CTAs/SM.
// ---------------------------------------------------------------------------
#define BM 128
#define BN 128
#define BK 32
#define ASTR 36
#define BSTR 132
#define NSTAGE 3

#define GEMM_SMEM_BYTES ((NSTAGE * BM * ASTR + NSTAGE * BK * BSTR) * 4)

__device__ __forceinline__ void gemm_body(
    const float* __restrict__ A, const float* __restrict__ Bm,
    const float* __restrict__ bias, float* __restrict__ C,
    int M, int N, int K)
{
    extern __shared__ float smd[];
    float* As = smd;                       // NSTAGE stages, BM x ASTR
    float* Bs = As + NSTAGE * BM * ASTR;   // NSTAGE stages, BK x BSTR
    float* biasT = As;                     // overlapped: used before staging

    const int tid = threadIdx.x;
    const int m0 = blockIdx.y * BM;
    const int n0 = blockIdx.x * BN;

    // Replicated bias tile (16 rows) in As stage-0 region, consumed into
    // accumulator fragments before any cp.async staging overwrites it.
    for (int i = tid; i < 16 * BN; i += 256) {
        int rr = i >> 7, cc = i & 127;
        biasT[rr * BSTR + cc] = bias[n0 + cc];
    }
    __syncthreads();

    const int w  = tid >> 5;
    const int wm = w >> 2;   // 0..1
    const int wn = w & 3;    // 0..3

    wmma::fragment<wmma::accumulator, 16, 16, 8, float> acc[4][2];
#pragma unroll
    for (int i = 0; i < 4; i++)
#pragma unroll
        for (int j = 0; j < 2; j++)
            wmma::load_matrix_sync(acc[i][j], &biasT[wn * 32 + j * 16], BSTR,
                                   wmma::mem_row_major);
    __syncthreads();  // done reading biasT; As region reusable

    // Per-thread staging coordinates (8 x 16B cp.async per stage)
    const int arow = tid >> 3, ac4 = (tid & 7) * 4;     // A: 128 rows x 8 f4
    const int brow = tid >> 5, bc4 = (tid & 31) * 4;    // B: 32 rows x 32 f4

    const int T = K / BK;

    // Prologue: stage tiles 0 and 1 (one commit group each)
#pragma unroll
    for (int pt = 0; pt < 2; pt++) {
        const int kt = pt * BK;
        const float* ag = &A[(size_t)(m0 + arow) * K + kt + ac4];
        const float* bg = &Bm[(size_t)(kt + brow) * N + n0 + bc4];
        float* asd = &As[pt * BM * ASTR];
        float* bsd = &Bs[pt * BK * BSTR];
#pragma unroll
        for (int p = 0; p < 4; p++)
            cpa16(&asd[(arow + p * 32) * ASTR + ac4], ag + (size_t)(p * 32) * K);
#pragma unroll
        for (int p = 0; p < 4; p++)
            cpa16(&bsd[(brow + p * 8) * BSTR + bc4], bg + (size_t)(p * 8) * N);
        cpa_commit();
    }

    for (int t = 0; t < T; t++) {
        if (t + 2 < T) {
            const int st = (t + 2) % NSTAGE;
            const int kt = (t + 2) * BK;
            const float* ag = &A[(size_t)(m0 + arow) * K + kt + ac4];
            const float* bg = &Bm[(size_t)(kt + brow) * N + n0 + bc4];
            float* asd = &As[st * BM * ASTR];
            float* bsd = &Bs[st * BK * BSTR];
#pragma unroll
            for (int p = 0; p < 4; p++)
                cpa16(&asd[(arow + p * 32) * ASTR + ac4], ag + (size_t)(p * 32) * K);
#pragma unroll
            for (int p = 0; p < 4; p++)
                cpa16(&bsd[(brow + p * 8) * BSTR + bc4], bg + (size_t)(p * 8) * N);
            cpa_commit();
            cpa_wait<2>();
        } else if (t + 2 == T) {
            cpa_wait<1>();
        } else {
            cpa_wait<0>();
        }
        __syncthreads();

        const float* asrc = &As[(t % NSTAGE) * BM * ASTR];
        const float* bsrc = &Bs[(t % NSTAGE) * BK * BSTR];

#pragma unroll
        for (int kk = 0; kk < BK; kk += 8) {
            wmma::fragment<wmma::matrix_a, 16, 16, 8, wmma::precision::tf32,
                           wmma::row_major> af[4];
            wmma::fragment<wmma::matrix_b, 16, 16, 8, wmma::precision::tf32,
                           wmma::row_major> bf[2];
#pragma unroll
            for (int i = 0; i < 4; i++)
                wmma::load_matrix_sync(af[i], &asrc[(wm * 64 + i * 16) * ASTR + kk], ASTR);
#pragma unroll
            for (int j = 0; j < 2; j++)
                wmma::load_matrix_sync(bf[j], &bsrc[kk * BSTR + wn * 32 + j * 16], BSTR);
#pragma unroll
            for (int i = 0; i < 4; i++)
#pragma unroll
                for (int j = 0; j < 2; j++)
                    wmma::mma_sync(acc[i][j], af[i], bf[j], acc[i][j]);
        }
        __syncthreads();  // all warps done with this stage before refill
    }

#pragma unroll
    for (int i = 0; i < 4; i++)
#pragma unroll
        for (int j = 0; j < 2; j++)
            wmma::store_matrix_sync(
                &C[(size_t)(m0 + wm * 64 + i * 16) * N + n0 + wn * 32 + j * 16],
                acc[i][j], N, wmma::mem_row_major);
}

__global__ __launch_bounds__(256, 2) void gemm_qkv_kernel()
{
    gemm_body(g_x, g_wqkv, nullptr, g_qkv, MROWS, C3, CC);
}

__global__ __launch_bounds__(256, 2) void gemm_proj_kernel(float* __restrict__ C)
{
    gemm_body(g_att, g_wproj, nullptr, C, MROWS, CC, CC);
}

// Bias pointers passed via globals to keep gemm_body signature simple
__device__ const float* gb_bias_qkv;
__device__ const float* gb_bias_proj;

// Re-define kernels properly with bias parameter instead:
__global__ __launch_bounds__(256, 2) void gemm_qkv_k(
    const float* __restrict__ bias)
{
    gemm_body(g_x, g_wqkv, bias, g_qkv, MROWS, C3, CC);
}

__global__ __launch_bounds__(256, 2) void gemm_proj_k(
    const float* __restrict__ bias, float* __restrict__ C)
{
    gemm_body(g_att, g_wproj, bias, C, MROWS, CC, CC);
}

// ---------------------------------------------------------------------------
// Fused attention (SIMT, round-2 version): one CTA per (batch, head).
// Output rounded to tf32 (it feeds the proj GEMM).
// ---------------------------------------------------------------------------
#define KSTR 68

#define SM_K   (224 * KSTR)
#define SM_V   (196 * KSTR)
#define SM_RH  (27 * KSTR)
#define SM_RW  (27 * KSTR)
#define SM_Q   (8 * 4 * KSTR)
#define SM_P   (8 * 4 * 200)
#define SM_REL (8 * 4 * 28)
#define ATTN_SMEM_FLOATS (SM_K + SM_V + SM_RH + SM_RW + SM_Q + SM_P + SM_REL)
#define ATTN_SMEM_BYTES (ATTN_SMEM_FLOATS * 4)

__global__ __launch_bounds__(256) void attn_kernel(
    const float* __restrict__ rph, const float* __restrict__ rpw)
{
    extern __shared__ float sm[];
    float* kS  = sm;
    float* vS  = kS + SM_K;
    float* RhS = vS + SM_V;
    float* RwS = RhS + SM_RH;
    float* qsm = RwS + SM_RW;
    float* pbf = qsm + SM_Q;
    float* rlb = pbf + SM_P;

    const int tid  = threadIdx.x;
    const int head = blockIdx.x;
    const int b = head / NHEAD;
    const int h = head % NHEAD;

    const float* gbase = g_qkv + (size_t)b * HWSZ * C3 + h * HDIM;

    for (int i = tid; i < HWSZ * HDIM; i += 256) {
        int j = i >> 6, d = i & 63;
        const float* p = gbase + (size_t)j * C3 + d;
        kS[j * KSTR + d] = p[768];
        vS[j * KSTR + d] = p[1536];
    }
    for (int i = tid; i < 28 * KSTR; i += 256) kS[196 * KSTR + i] = 0.f;
    for (int i = tid; i < 27 * HDIM; i += 256) {
        int r = i >> 6, d = i & 63;
        RhS[r * KSTR + d] = rph[i];
        RwS[r * KSTR + d] = rpw[i];
    }
    __syncthreads();

    const int wid = tid >> 5, lane = tid & 31;
    float* qw = qsm + wid * 4 * KSTR;
    float* pw = pbf + wid * 800;
    float* rb = rlb + wid * 112;

    for (int g = wid; g < 49; g += 8) {
        const int r0 = g * 4;

        for (int i = lane; i < 4 * HDIM; i += 32) {
            int rr = i >> 6, d = i & 63;
            qw[rr * KSTR + d] = gbase[(size_t)(r0 + rr) * C3 + d];
        }
        __syncwarp();

        for (int t = lane; t < 112; t += 32) {
            int rr = t / 28, wch = t % 28;
            int r = r0 + rr;
            const float* tab;
            int row;
            if (wch < 14) { row = r / 14 - wch + 13;        tab = RhS; }
            else          { row = r % 14 - (wch - 14) + 13; tab = RwS; }
            const float* qp = qw + rr * KSTR;
            const float* tp = tab + row * KSTR;
            float s = 0.f;
#pragma unroll
            for (int d = 0; d < 64; d++) s += qp[d] * tp[d];
            rb[rr * 28 + wch] = s;
        }
        __syncwarp();

        float acc[4][7];
#pragma unroll
        for (int rr = 0; rr < 4; rr++)
#pragma unroll
            for (int jj = 0; jj < 7; jj++) acc[rr][jj] = 0.f;

#pragma unroll 4
        for (int d0 = 0; d0 < 64; d0 += 4) {
            float4 qv[4];
#pragma unroll
            for (int rr = 0; rr < 4; rr++)
                qv[rr] = *(const float4*)(qw + rr * KSTR + d0);
#pragma unroll
            for (int jj = 0; jj < 7; jj++) {
                int j = lane + jj * 32;
                float4 kv = *(const float4*)(kS + j * KSTR + d0);
#pragma unroll
                for (int rr = 0; rr < 4; rr++)
                    acc[rr][jj] += qv[rr].x * kv.x + qv[rr].y * kv.y +
                                   qv[rr].z * kv.z + qv[rr].w * kv.w;
            }
        }

        float inv[4];
#pragma unroll
        for (int rr = 0; rr < 4; rr++) {
            float m = -1e30f;
#pragma unroll
            for (int jj = 0; jj < 7; jj++) {
                int j = lane + jj * 32;
                if (j < HWSZ) {
                    float s = acc[rr][jj] * 0.125f
                            + rb[rr * 28 + j / 14]
                            + rb[rr * 28 + 14 + j % 14];
                    acc[rr][jj] = s;
                    m = fmaxf(m, s);
                }
            }
#pragma unroll
            for (int o = 16; o > 0; o >>= 1)
                m = fmaxf(m, __shfl_xor_sync(0xffffffffu, m, o));
            float lsum = 0.f;
#pragma unroll
            for (int jj = 0; jj < 7; jj++) {
                int j = lane + jj * 32;
                if (j < HWSZ) {
                    float e = __expf(acc[rr][jj] - m);
                    pw[rr * 200 + j] = e;
                    lsum += e;
                }
            }
#pragma unroll
            for (int o = 16; o > 0; o >>= 1)
                lsum += __shfl_xor_sync(0xffffffffu, lsum, o);
            inv[rr] = 1.f / lsum;
        }
        __syncwarp();

        float o0[4] = {0, 0, 0, 0}, o1[4] = {0, 0, 0, 0};
#pragma unroll 2
        for (int j = 0; j < HWSZ; j++) {
            float2 vv = *(const float2*)(vS + j * KSTR + 2 * lane);
#pragma unroll
            for (int rr = 0; rr < 4; rr++) {
                float p = pw[rr * 200 + j];
                o0[rr] += p * vv.x;
                o1[rr] += p * vv.y;
            }
        }

        float* gout = g_att + ((size_t)b * HWSZ + r0) * CC + h * HDIM;
#pragma unroll
        for (int rr = 0; rr < 4; rr++) {
            float2 res;
            res.x = f2tf32(o0[rr] * inv[rr]);   // pre-round for proj GEMM
            res.y = f2tf32(o1[rr] * inv[rr]);
            *(float2*)(gout + rr * CC + 2 * lane) = res;
        }
        __syncwarp();
    }
}

// ---------------------------------------------------------------------------
extern "C" void kernel_launch(void* const* d_in, const int* in_sizes, int n_in,
                              void* d_out, int out_size)
{
    const float* x      = (const float*)d_in[0]; // (25088, 768)
    const float* w_qkv  = (const float*)d_in[1]; // (768, 2304)
    const float* b_qkv  = (const float*)d_in[2]; // (2304,)
    const float* rph    = (const float*)d_in[3]; // (27, 64)
    const float* rpw    = (const float*)d_in[4]; // (27, 64)
    const float* w_proj = (const float*)d_in[5]; // (768, 768)
    const float* b_proj = (const float*)d_in[6]; // (768,)
    float* out = (float*)d_out;                  // (25088, 768)

    float *d_x, *d_wqkv, *d_wproj;
    cudaGetSymbolAddress((void**)&d_x, g_x);
    cudaGetSymbolAddress((void**)&d_wqkv, g_wqkv);
    cudaGetSymbolAddress((void**)&d_wproj, g_wproj);

    cudaFuncSetAttribute(gemm_qkv_k,
                         cudaFuncAttributeMaxDynamicSharedMemorySize,
                         GEMM_SMEM_BYTES);
    cudaFuncSetAttribute(gemm_proj_k,
                         cudaFuncAttributeMaxDynamicSharedMemorySize,
                         GEMM_SMEM_BYTES);
    cudaFuncSetAttribute(attn_kernel,
                         cudaFuncAttributeMaxDynamicSharedMemorySize,
                         ATTN_SMEM_BYTES);

    // Pre-round GEMM inputs to tf32 (RN)
    {
        int n4 = MROWS * CC / 4;
        round_tf32_kernel<<<(n4 + 255) / 256, 256>>>(x, d_x, n4);
        n4 = CC * C3 / 4;
        round_tf32_kernel<<<(n4 + 255) / 256, 256>>>(w_qkv, d_wqkv, n4);
        n4 = CC * CC / 4;
        round_tf32_kernel<<<(n4 + 255) / 256, 256>>>(w_proj, d_wproj, n4);
    }

    dim3 g1(C3 / BN, MROWS / BM);   // 18 x 196
    gemm_qkv_k<<<g1, 256, GEMM_SMEM_BYTES>>>(b_qkv);

    attn_kernel<<<NHEADS_TOTAL, 256, ATTN_SMEM_BYTES>>>(rph, rpw);

    dim3 g2(CC / BN, MROWS / BM);   // 6 x 196
    gemm_proj_k<<<g2, 256, GEMM_SMEM_BYTES>>>(b_proj, out);
}

// round 6
// speedup vs baseline: 1.6761x; 1.6761x over previous
#include <cuda_runtime.h>
#include <mma.h>
#include <cstddef>
#include <cstdint>

using namespace nvcuda;

// Problem constants
#define BATCH 128
#define HH 14
#define WW 14
#define CC 768
#define NHEAD 12
#define HDIM 64
#define HWSZ 196          // 14*14
#define C3 2304           // 3*C
#define MROWS 25088       // BATCH*HWSZ
#define NHEADS_TOTAL 1536 // BATCH*NHEAD

typedef unsigned long long u64;

// Scratch buffers (device globals: no allocation allowed)
__device__ float g_qkv[(size_t)MROWS * C3];  // (B, HW, 3, NH, HD) fp32
__device__ float g_att[(size_t)MROWS * CC];  // attention out, tf32-rounded
__device__ float g_x[(size_t)MROWS * CC];    // x, tf32-rounded
__device__ float g_wqkv[(size_t)CC * C3];    // w_qkv, tf32-rounded
__device__ float g_wproj[(size_t)CC * CC];   // w_proj, tf32-rounded

// ---------------------------------------------------------------------------
// helpers
// ---------------------------------------------------------------------------
__device__ __forceinline__ float f2tf32(float f) {
    uint32_t r;
    asm("cvt.rna.tf32.f32 %0, %1;" : "=r"(r) : "f"(f));
    return __uint_as_float(r);
}

__global__ void round_tf32_kernel(const float* __restrict__ in,
                                  float* __restrict__ out, int n4)
{
    int i = blockIdx.x * blockDim.x + threadIdx.x;
    if (i < n4) {
        float4 v = ((const float4*)in)[i];
        v.x = f2tf32(v.x); v.y = f2tf32(v.y);
        v.z = f2tf32(v.z); v.w = f2tf32(v.w);
        ((float4*)out)[i] = v;
    }
}

// packed f32x2 ops (Blackwell)
__device__ __forceinline__ u64 fma2(u64 a, u64 b, u64 c) {
    u64 d;
    asm("fma.rn.f32x2 %0, %1, %2, %3;" : "=l"(d) : "l"(a), "l"(b), "l"(c));
    return d;
}
__device__ __forceinline__ u64 pack2(float lo, float hi) {
    u64 d;
    asm("mov.b64 %0, {%1, %2};" : "=l"(d) : "f"(lo), "f"(hi));
    return d;
}
__device__ __forceinline__ float hsum2(u64 v) {
    float a, b;
    asm("mov.b64 {%0, %1}, %2;" : "=f"(a), "=f"(b) : "l"(v));
    return a + b;
}

__device__ __forceinline__ void cpa16(void* s, const void* g) {
    uint32_t sa = (uint32_t)__cvta_generic_to_shared(s);
    asm volatile("cp.async.cg.shared.global [%0], [%1], 16;\n" ::"r"(sa), "l"(g));
}
__device__ __forceinline__ void cpa_commit() {
    asm volatile("cp.async.commit_group;\n" ::);
}
template <int N>
__device__ __forceinline__ void cpa_wait() {
    asm volatile("cp.async.wait_group %0;\n" ::"n"(N));
}

// ---------------------------------------------------------------------------
// Pipelined tf32 GEMM (round-2 geometry), inputs pre-rounded (no in-loop cvt)
// C = A(MxK) @ B(KxN) + bias.  BM=BN=128, BK=32, 2-stage, 256 thr, 2 CTA/SM
// ---------------------------------------------------------------------------
#define BM 128
#define BN 128
#define BK 32
#define ASTR 40
#define BSTR 136

#define GEMM_SMEM_BYTES (2 * BM * ASTR * 4 + 2 * BK * BSTR * 4 + 16 * BSTR * 4)

__device__ __forceinline__ void gemm_body(
    const float* __restrict__ A, const float* __restrict__ Bm,
    const float* __restrict__ bias, float* __restrict__ C,
    int M, int N, int K)
{
    extern __shared__ float smd[];
    float* As    = smd;
    float* Bs    = As + 2 * BM * ASTR;
    float* biasT = Bs + 2 * BK * BSTR;

    const int tid = threadIdx.x;
    const int m0 = blockIdx.y * BM;
    const int n0 = blockIdx.x * BN;

    for (int i = tid; i < 16 * BN; i += 256) {
        int rr = i >> 7, cc = i & 127;
        biasT[rr * BSTR + cc] = bias[n0 + cc];
    }
    __syncthreads();

    const int w  = tid >> 5;
    const int wm = w >> 2;
    const int wn = w & 3;

    wmma::fragment<wmma::accumulator, 16, 16, 8, float> acc[4][2];
#pragma unroll
    for (int i = 0; i < 4; i++)
#pragma unroll
        for (int j = 0; j < 2; j++)
            wmma::load_matrix_sync(acc[i][j], &biasT[wn * 32 + j * 16], BSTR,
                                   wmma::mem_row_major);

    const int arow = tid >> 3, ac4 = (tid & 7) * 4;
    const int brow = tid >> 5, bc4 = (tid & 31) * 4;

    const int T = K / BK;

    {
        const float* ag = &A[(size_t)(m0 + arow) * K + ac4];
        const float* bg = &Bm[(size_t)brow * N + n0 + bc4];
#pragma unroll
        for (int p = 0; p < 4; p++)
            cpa16(&As[(arow + p * 32) * ASTR + ac4], ag + (size_t)(p * 32) * K);
#pragma unroll
        for (int p = 0; p < 4; p++)
            cpa16(&Bs[(brow + p * 8) * BSTR + bc4], bg + (size_t)(p * 8) * N);
        cpa_commit();
    }

    for (int t = 0; t < T; t++) {
        if (t + 1 < T) {
            const int st = (t + 1) & 1;
            const int kt = (t + 1) * BK;
            const float* ag = &A[(size_t)(m0 + arow) * K + kt + ac4];
            const float* bg = &Bm[(size_t)(kt + brow) * N + n0 + bc4];
            float* asd = &As[st * BM * ASTR];
            float* bsd = &Bs[st * BK * BSTR];
#pragma unroll
            for (int p = 0; p < 4; p++)
                cpa16(&asd[(arow + p * 32) * ASTR + ac4], ag + (size_t)(p * 32) * K);
#pragma unroll
            for (int p = 0; p < 4; p++)
                cpa16(&bsd[(brow + p * 8) * BSTR + bc4], bg + (size_t)(p * 8) * N);
            cpa_commit();
            cpa_wait<1>();
        } else {
            cpa_wait<0>();
        }
        __syncthreads();

        const float* asrc = &As[(t & 1) * BM * ASTR];
        const float* bsrc = &Bs[(t & 1) * BK * BSTR];

#pragma unroll
        for (int kk = 0; kk < BK; kk += 8) {
            wmma::fragment<wmma::matrix_a, 16, 16, 8, wmma::precision::tf32,
                           wmma::row_major> af[4];
            wmma::fragment<wmma::matrix_b, 16, 16, 8, wmma::precision::tf32,
                           wmma::row_major> bf[2];
#pragma unroll
            for (int i = 0; i < 4; i++)
                wmma::load_matrix_sync(af[i], &asrc[(wm * 64 + i * 16) * ASTR + kk], ASTR);
#pragma unroll
            for (int j = 0; j < 2; j++)
                wmma::load_matrix_sync(bf[j], &bsrc[kk * BSTR + wn * 32 + j * 16], BSTR);
#pragma unroll
            for (int i = 0; i < 4; i++)
#pragma unroll
                for (int j = 0; j < 2; j++)
                    wmma::mma_sync(acc[i][j], af[i], bf[j], acc[i][j]);
        }
        __syncthreads();
    }

#pragma unroll
    for (int i = 0; i < 4; i++)
#pragma unroll
        for (int j = 0; j < 2; j++)
            wmma::store_matrix_sync(
                &C[(size_t)(m0 + wm * 64 + i * 16) * N + n0 + wn * 32 + j * 16],
                acc[i][j], N, wmma::mem_row_major);
}

__global__ __launch_bounds__(256, 2) void gemm_qkv_k(const float* __restrict__ bias)
{
    gemm_body(g_x, g_wqkv, bias, g_qkv, MROWS, C3, CC);
}

__global__ __launch_bounds__(256, 2) void gemm_proj_k(
    const float* __restrict__ bias, float* __restrict__ C)
{
    gemm_body(g_att, g_wproj, bias, C, MROWS, CC, CC);
}

// ---------------------------------------------------------------------------
// Fused attention with packed f32x2 FMA. One CTA per (batch, head).
// ---------------------------------------------------------------------------
#define KSTR 68

#define SM_K   (224 * KSTR)
#define SM_V   (196 * KSTR)
#define SM_RH  (27 * KSTR)
#define SM_RW  (27 * KSTR)
#define SM_Q   (8 * 4 * KSTR)
#define SM_P   (8 * 4 * 200)
#define SM_REL (8 * 4 * 28)
#define ATTN_SMEM_FLOATS (SM_K + SM_V + SM_RH + SM_RW + SM_Q + SM_P + SM_REL)
#define ATTN_SMEM_BYTES (ATTN_SMEM_FLOATS * 4)

__global__ __launch_bounds__(256) void attn_kernel(
    const float* __restrict__ rph, const float* __restrict__ rpw)
{
    extern __shared__ float sm[];
    float* kS  = sm;
    float* vS  = kS + SM_K;
    float* RhS = vS + SM_V;
    float* RwS = RhS + SM_RH;
    float* qsm = RwS + SM_RW;
    float* pbf = qsm + SM_Q;
    float* rlb = pbf + SM_P;

    const int tid  = threadIdx.x;
    const int head = blockIdx.x;
    const int b = head / NHEAD;
    const int h = head % NHEAD;

    const float* gbase = g_qkv + (size_t)b * HWSZ * C3 + h * HDIM;

    for (int i = tid; i < HWSZ * HDIM; i += 256) {
        int j = i >> 6, d = i & 63;
        const float* p = gbase + (size_t)j * C3 + d;
        kS[j * KSTR + d] = p[768];
        vS[j * KSTR + d] = p[1536];
    }
    for (int i = tid; i < 28 * KSTR; i += 256) kS[196 * KSTR + i] = 0.f;
    for (int i = tid; i < 27 * HDIM; i += 256) {
        int r = i >> 6, d = i & 63;
        RhS[r * KSTR + d] = rph[i];
        RwS[r * KSTR + d] = rpw[i];
    }
    __syncthreads();

    const int wid = tid >> 5, lane = tid & 31;
    float* qw = qsm + wid * 4 * KSTR;
    float* pw = pbf + wid * 800;
    float* rb = rlb + wid * 112;

    for (int g = wid; g < 49; g += 8) {
        const int r0 = g * 4;

        for (int i = lane; i < 4 * HDIM; i += 32) {
            int rr = i >> 6, d = i & 63;
            qw[rr * KSTR + d] = gbase[(size_t)(r0 + rr) * C3 + d];
        }
        __syncwarp();

        // rel-pos dots (packed along d)
        for (int t = lane; t < 112; t += 32) {
            int rr = t / 28, wch = t % 28;
            int r = r0 + rr;
            const float* tab;
            int row;
            if (wch < 14) { row = r / 14 - wch + 13;        tab = RhS; }
            else          { row = r % 14 - (wch - 14) + 13; tab = RwS; }
            const u64* qp = (const u64*)(qw + rr * KSTR);
            const u64* tp = (const u64*)(tab + row * KSTR);
            u64 s2 = 0ull;
#pragma unroll
            for (int d = 0; d < 32; d++) s2 = fma2(qp[d], tp[d], s2);
            rb[rr * 28 + wch] = hsum2(s2);
        }
        __syncwarp();

        // QK^T: packed along d (d, d+1 halves), horizontal-summed at the end
        u64 acc2[4][7];
#pragma unroll
        for (int rr = 0; rr < 4; rr++)
#pragma unroll
            for (int jj = 0; jj < 7; jj++) acc2[rr][jj] = 0ull;

#pragma unroll 4
        for (int d0 = 0; d0 < 64; d0 += 4) {
            ulonglong2 qv[4];
#pragma unroll
            for (int rr = 0; rr < 4; rr++)
                qv[rr] = *(const ulonglong2*)(qw + rr * KSTR + d0);
#pragma unroll
            for (int jj = 0; jj < 7; jj++) {
                int j = lane + jj * 32;  // pad rows (>=196) are zero
                ulonglong2 kv = *(const ulonglong2*)(kS + j * KSTR + d0);
#pragma unroll
                for (int rr = 0; rr < 4; rr++) {
                    acc2[rr][jj] = fma2(kv.x, qv[rr].x, acc2[rr][jj]);
                    acc2[rr][jj] = fma2(kv.y, qv[rr].y, acc2[rr][jj]);
                }
            }
        }

        // softmax (scale 1/8, + rel bias)
        float inv[4];
#pragma unroll
        for (int rr = 0; rr < 4; rr++) {
            float vals[7];
            float m = -1e30f;
#pragma unroll
            for (int jj = 0; jj < 7; jj++) {
                int j = lane + jj * 32;
                if (j < HWSZ) {
                    float s = hsum2(acc2[rr][jj]) * 0.125f
                            + rb[rr * 28 + j / 14]
                            + rb[rr * 28 + 14 + j % 14];
                    vals[jj] = s;
                    m = fmaxf(m, s);
                }
            }
#pragma unroll
            for (int o = 16; o > 0; o >>= 1)
                m = fmaxf(m, __shfl_xor_sync(0xffffffffu, m, o));
            float lsum = 0.f;
#pragma unroll
            for (int jj = 0; jj < 7; jj++) {
                int j = lane + jj * 32;
                if (j < HWSZ) {
                    float e = __expf(vals[jj] - m);
                    pw[rr * 200 + j] = e;
                    lsum += e;
                }
            }
#pragma unroll
            for (int o = 16; o > 0; o >>= 1)
                lsum += __shfl_xor_sync(0xffffffffu, lsum, o);
            inv[rr] = 1.f / lsum;
        }
        __syncwarp();

        // P @ V: packed along key pairs (j, j+1); lane owns dims 2*lane, +1
        u64 o20[4] = {0ull, 0ull, 0ull, 0ull};
        u64 o21[4] = {0ull, 0ull, 0ull, 0ull};
#pragma unroll 2
        for (int j = 0; j < HWSZ; j += 2) {
            float2 va = *(const float2*)(vS + j * KSTR + 2 * lane);
            float2 vb = *(const float2*)(vS + (j + 1) * KSTR + 2 * lane);
            u64 vx = pack2(va.x, vb.x);
            u64 vy = pack2(va.y, vb.y);
#pragma unroll
            for (int rr = 0; rr < 4; rr++) {
                u64 pp = *(const u64*)(pw + rr * 200 + j);
                o20[rr] = fma2(pp, vx, o20[rr]);
                o21[rr] = fma2(pp, vy, o21[rr]);
            }
        }

        float* gout = g_att + ((size_t)b * HWSZ + r0) * CC + h * HDIM;
#pragma unroll
        for (int rr = 0; rr < 4; rr++) {
            float2 res;
            res.x = f2tf32(hsum2(o20[rr]) * inv[rr]);  // pre-round for proj GEMM
            res.y = f2tf32(hsum2(o21[rr]) * inv[rr]);
            *(float2*)(gout + rr * CC + 2 * lane) = res;
        }
        __syncwarp();
    }
}

// ---------------------------------------------------------------------------
extern "C" void kernel_launch(void* const* d_in, const int* in_sizes, int n_in,
                              void* d_out, int out_size)
{
    const float* x      = (const float*)d_in[0]; // (25088, 768)
    const float* w_qkv  = (const float*)d_in[1]; // (768, 2304)
    const float* b_qkv  = (const float*)d_in[2]; // (2304,)
    const float* rph    = (const float*)d_in[3]; // (27, 64)
    const float* rpw    = (const float*)d_in[4]; // (27, 64)
    const float* w_proj = (const float*)d_in[5]; // (768, 768)
    const float* b_proj = (const float*)d_in[6]; // (768,)
    float* out = (float*)d_out;                  // (25088, 768)

    float *d_x, *d_wqkv, *d_wproj;
    cudaGetSymbolAddress((void**)&d_x, g_x);
    cudaGetSymbolAddress((void**)&d_wqkv, g_wqkv);
    cudaGetSymbolAddress((void**)&d_wproj, g_wproj);

    cudaFuncSetAttribute(gemm_qkv_k,
                         cudaFuncAttributeMaxDynamicSharedMemorySize,
                         GEMM_SMEM_BYTES);
    cudaFuncSetAttribute(gemm_proj_k,
                         cudaFuncAttributeMaxDynamicSharedMemorySize,
                         GEMM_SMEM_BYTES);
    cudaFuncSetAttribute(attn_kernel,
                         cudaFuncAttributeMaxDynamicSharedMemorySize,
                         ATTN_SMEM_BYTES);

    // Pre-round GEMM inputs to tf32 (RN)
    {
        int n4 = MROWS * CC / 4;
        round_tf32_kernel<<<(n4 + 255) / 256, 256>>>(x, d_x, n4);
        n4 = CC * C3 / 4;
        round_tf32_kernel<<<(n4 + 255) / 256, 256>>>(w_qkv, d_wqkv, n4);
        n4 = CC * CC / 4;
        round_tf32_kernel<<<(n4 + 255) / 256, 256>>>(w_proj, d_wproj, n4);
    }

    dim3 g1(C3 / BN, MROWS / BM);   // 18 x 196
    gemm_qkv_k<<<g1, 256, GEMM_SMEM_BYTES>>>(b_qkv);

    attn_kernel<<<NHEADS_TOTAL, 256, ATTN_SMEM_BYTES>>>(rph, rpw);

    dim3 g2(CC / BN, MROWS / BM);   // 6 x 196
    gemm_proj_k<<<g2, 256, GEMM_SMEM_BYTES>>>(b_proj, out);
}

// round 7
// speedup vs baseline: 1.7850x; 1.0650x over previous
#include <cuda_runtime.h>
#include <mma.h>
#include <cstddef>
#include <cstdint>

using namespace nvcuda;

// Problem constants
#define BATCH 128
#define HH 14
#define WW 14
#define CC 768
#define NHEAD 12
#define HDIM 64
#define HWSZ 196          // 14*14
#define C3 2304           // 3*C
#define MROWS 25088       // BATCH*HWSZ
#define NHEADS_TOTAL 1536 // BATCH*NHEAD

typedef unsigned long long u64;

// Scratch buffers (device globals: no allocation allowed)
__device__ float g_qkv[(size_t)MROWS * C3];  // (B, HW, 3, NH, HD) fp32
__device__ float g_att[(size_t)MROWS * CC];  // attention out, tf32-rounded
__device__ float g_x[(size_t)MROWS * CC];    // x, tf32-rounded
__device__ float g_wqkv[(size_t)CC * C3];    // w_qkv, tf32-rounded
__device__ float g_wproj[(size_t)CC * CC];   // w_proj, tf32-rounded

// ---------------------------------------------------------------------------
// helpers
// ---------------------------------------------------------------------------
__device__ __forceinline__ float f2tf32(float f) {
    uint32_t r;
    asm("cvt.rna.tf32.f32 %0, %1;" : "=r"(r) : "f"(f));
    return __uint_as_float(r);
}

__global__ void round_tf32_kernel(const float* __restrict__ in,
                                  float* __restrict__ out, int n4)
{
    int i = blockIdx.x * blockDim.x + threadIdx.x;
    if (i < n4) {
        float4 v = ((const float4*)in)[i];
        v.x = f2tf32(v.x); v.y = f2tf32(v.y);
        v.z = f2tf32(v.z); v.w = f2tf32(v.w);
        ((float4*)out)[i] = v;
    }
}

// packed f32x2 ops (Blackwell)
__device__ __forceinline__ u64 fma2(u64 a, u64 b, u64 c) {
    u64 d;
    asm("fma.rn.f32x2 %0, %1, %2, %3;" : "=l"(d) : "l"(a), "l"(b), "l"(c));
    return d;
}
__device__ __forceinline__ u64 pack2(float lo, float hi) {
    u64 d;
    asm("mov.b64 %0, {%1, %2};" : "=l"(d) : "f"(lo), "f"(hi));
    return d;
}
__device__ __forceinline__ float hsum2(u64 v) {
    float a, b;
    asm("mov.b64 {%0, %1}, %2;" : "=f"(a), "=f"(b) : "l"(v));
    return a + b;
}

__device__ __forceinline__ void cpa16(void* s, const void* g) {
    uint32_t sa = (uint32_t)__cvta_generic_to_shared(s);
    asm volatile("cp.async.cg.shared.global [%0], [%1], 16;\n" ::"r"(sa), "l"(g));
}
__device__ __forceinline__ void cpa_commit() {
    asm volatile("cp.async.commit_group;\n" ::);
}
template <int N>
__device__ __forceinline__ void cpa_wait() {
    asm volatile("cp.async.wait_group %0;\n" ::"n"(N));
}

// ---------------------------------------------------------------------------
// Pipelined tf32 GEMM (round-2 geometry), inputs pre-rounded (no in-loop cvt)
// C = A(MxK) @ B(KxN) + bias.  BM=BN=128, BK=32, 2-stage, 256 thr, 2 CTA/SM
// ---------------------------------------------------------------------------
#define BM 128
#define BN 128
#define BK 32
#define ASTR 40
#define BSTR 136

#define GEMM_SMEM_BYTES (2 * BM * ASTR * 4 + 2 * BK * BSTR * 4 + 16 * BSTR * 4)

__device__ __forceinline__ void gemm_body(
    const float* __restrict__ A, const float* __restrict__ Bm,
    const float* __restrict__ bias, float* __restrict__ C,
    int M, int N, int K)
{
    extern __shared__ float smd[];
    float* As    = smd;
    float* Bs    = As + 2 * BM * ASTR;
    float* biasT = Bs + 2 * BK * BSTR;

    const int tid = threadIdx.x;
    const int m0 = blockIdx.y * BM;
    const int n0 = blockIdx.x * BN;

    for (int i = tid; i < 16 * BN; i += 256) {
        int rr = i >> 7, cc = i & 127;
        biasT[rr * BSTR + cc] = bias[n0 + cc];
    }
    __syncthreads();

    const int w  = tid >> 5;
    const int wm = w >> 2;
    const int wn = w & 3;

    wmma::fragment<wmma::accumulator, 16, 16, 8, float> acc[4][2];
#pragma unroll
    for (int i = 0; i < 4; i++)
#pragma unroll
        for (int j = 0; j < 2; j++)
            wmma::load_matrix_sync(acc[i][j], &biasT[wn * 32 + j * 16], BSTR,
                                   wmma::mem_row_major);

    const int arow = tid >> 3, ac4 = (tid & 7) * 4;
    const int brow = tid >> 5, bc4 = (tid & 31) * 4;

    const int T = K / BK;

    {
        const float* ag = &A[(size_t)(m0 + arow) * K + ac4];
        const float* bg = &Bm[(size_t)brow * N + n0 + bc4];
#pragma unroll
        for (int p = 0; p < 4; p++)
            cpa16(&As[(arow + p * 32) * ASTR + ac4], ag + (size_t)(p * 32) * K);
#pragma unroll
        for (int p = 0; p < 4; p++)
            cpa16(&Bs[(brow + p * 8) * BSTR + bc4], bg + (size_t)(p * 8) * N);
        cpa_commit();
    }

    for (int t = 0; t < T; t++) {
        if (t + 1 < T) {
            const int st = (t + 1) & 1;
            const int kt = (t + 1) * BK;
            const float* ag = &A[(size_t)(m0 + arow) * K + kt + ac4];
            const float* bg = &Bm[(size_t)(kt + brow) * N + n0 + bc4];
            float* asd = &As[st * BM * ASTR];
            float* bsd = &Bs[st * BK * BSTR];
#pragma unroll
            for (int p = 0; p < 4; p++)
                cpa16(&asd[(arow + p * 32) * ASTR + ac4], ag + (size_t)(p * 32) * K);
#pragma unroll
            for (int p = 0; p < 4; p++)
                cpa16(&bsd[(brow + p * 8) * BSTR + bc4], bg + (size_t)(p * 8) * N);
            cpa_commit();
            cpa_wait<1>();
        } else {
            cpa_wait<0>();
        }
        __syncthreads();

        const float* asrc = &As[(t & 1) * BM * ASTR];
        const float* bsrc = &Bs[(t & 1) * BK * BSTR];

#pragma unroll
        for (int kk = 0; kk < BK; kk += 8) {
            wmma::fragment<wmma::matrix_a, 16, 16, 8, wmma::precision::tf32,
                           wmma::row_major> af[4];
            wmma::fragment<wmma::matrix_b, 16, 16, 8, wmma::precision::tf32,
                           wmma::row_major> bf[2];
#pragma unroll
            for (int i = 0; i < 4; i++)
                wmma::load_matrix_sync(af[i], &asrc[(wm * 64 + i * 16) * ASTR + kk], ASTR);
#pragma unroll
            for (int j = 0; j < 2; j++)
                wmma::load_matrix_sync(bf[j], &bsrc[kk * BSTR + wn * 32 + j * 16], BSTR);
#pragma unroll
            for (int i = 0; i < 4; i++)
#pragma unroll
                for (int j = 0; j < 2; j++)
                    wmma::mma_sync(acc[i][j], af[i], bf[j], acc[i][j]);
        }
        __syncthreads();
    }

#pragma unroll
    for (int i = 0; i < 4; i++)
#pragma unroll
        for (int j = 0; j < 2; j++)
            wmma::store_matrix_sync(
                &C[(size_t)(m0 + wm * 64 + i * 16) * N + n0 + wn * 32 + j * 16],
                acc[i][j], N, wmma::mem_row_major);
}

__global__ __launch_bounds__(256, 2) void gemm_qkv_k(const float* __restrict__ bias)
{
    gemm_body(g_x, g_wqkv, bias, g_qkv, MROWS, C3, CC);
}

__global__ __launch_bounds__(256, 2) void gemm_proj_k(
    const float* __restrict__ bias, float* __restrict__ C)
{
    gemm_body(g_att, g_wproj, bias, C, MROWS, CC, CC);
}

// ---------------------------------------------------------------------------
// Fused attention, packed f32x2 FMA, 512 threads (16 warps) per CTA for
// latency hiding. One CTA per (batch, head).
// ---------------------------------------------------------------------------
#define KSTR 68
#define NWARP 16
#define NTHR (NWARP * 32)

#define SM_K   (224 * KSTR)
#define SM_V   (196 * KSTR)
#define SM_RH  (27 * KSTR)
#define SM_RW  (27 * KSTR)
#define SM_Q   (NWARP * 4 * KSTR)
#define SM_P   (NWARP * 4 * 200)
#define SM_REL (NWARP * 4 * 28)
#define ATTN_SMEM_FLOATS (SM_K + SM_V + SM_RH + SM_RW + SM_Q + SM_P + SM_REL)
#define ATTN_SMEM_BYTES (ATTN_SMEM_FLOATS * 4)

__global__ __launch_bounds__(NTHR) void attn_kernel(
    const float* __restrict__ rph, const float* __restrict__ rpw)
{
    extern __shared__ float sm[];
    float* kS  = sm;
    float* vS  = kS + SM_K;
    float* RhS = vS + SM_V;
    float* RwS = RhS + SM_RH;
    float* qsm = RwS + SM_RW;
    float* pbf = qsm + SM_Q;
    float* rlb = pbf + SM_P;

    const int tid  = threadIdx.x;
    const int head = blockIdx.x;
    const int b = head / NHEAD;
    const int h = head % NHEAD;

    const float* gbase = g_qkv + (size_t)b * HWSZ * C3 + h * HDIM;

    for (int i = tid; i < HWSZ * HDIM; i += NTHR) {
        int j = i >> 6, d = i & 63;
        const float* p = gbase + (size_t)j * C3 + d;
        kS[j * KSTR + d] = p[768];
        vS[j * KSTR + d] = p[1536];
    }
    for (int i = tid; i < 28 * KSTR; i += NTHR) kS[196 * KSTR + i] = 0.f;
    for (int i = tid; i < 27 * HDIM; i += NTHR) {
        int r = i >> 6, d = i & 63;
        RhS[r * KSTR + d] = rph[i];
        RwS[r * KSTR + d] = rpw[i];
    }
    __syncthreads();

    const int wid = tid >> 5, lane = tid & 31;
    float* qw = qsm + wid * 4 * KSTR;
    float* pw = pbf + wid * 800;
    float* rb = rlb + wid * 112;

    for (int g = wid; g < 49; g += NWARP) {
        const int r0 = g * 4;

        for (int i = lane; i < 4 * HDIM; i += 32) {
            int rr = i >> 6, d = i & 63;
            qw[rr * KSTR + d] = gbase[(size_t)(r0 + rr) * C3 + d];
        }
        __syncwarp();

        // rel-pos dots (packed along d)
        for (int t = lane; t < 112; t += 32) {
            int rr = t / 28, wch = t % 28;
            int r = r0 + rr;
            const float* tab;
            int row;
            if (wch < 14) { row = r / 14 - wch + 13;        tab = RhS; }
            else          { row = r % 14 - (wch - 14) + 13; tab = RwS; }
            const u64* qp = (const u64*)(qw + rr * KSTR);
            const u64* tp = (const u64*)(tab + row * KSTR);
            u64 s2 = 0ull;
#pragma unroll
            for (int d = 0; d < 32; d++) s2 = fma2(qp[d], tp[d], s2);
            rb[rr * 28 + wch] = hsum2(s2);
        }
        __syncwarp();

        // QK^T: packed along d (d, d+1 halves), horizontal-summed at the end
        u64 acc2[4][7];
#pragma unroll
        for (int rr = 0; rr < 4; rr++)
#pragma unroll
            for (int jj = 0; jj < 7; jj++) acc2[rr][jj] = 0ull;

#pragma unroll 4
        for (int d0 = 0; d0 < 64; d0 += 4) {
            ulonglong2 qv[4];
#pragma unroll
            for (int rr = 0; rr < 4; rr++)
                qv[rr] = *(const ulonglong2*)(qw + rr * KSTR + d0);
#pragma unroll
            for (int jj = 0; jj < 7; jj++) {
                int j = lane + jj * 32;  // pad rows (>=196) are zero
                ulonglong2 kv = *(const ulonglong2*)(kS + j * KSTR + d0);
#pragma unroll
                for (int rr = 0; rr < 4; rr++) {
                    acc2[rr][jj] = fma2(kv.x, qv[rr].x, acc2[rr][jj]);
                    acc2[rr][jj] = fma2(kv.y, qv[rr].y, acc2[rr][jj]);
                }
            }
        }

        // softmax (scale 1/8, + rel bias)
        float inv[4];
#pragma unroll
        for (int rr = 0; rr < 4; rr++) {
            float vals[7];
            float m = -1e30f;
#pragma unroll
            for (int jj = 0; jj < 7; jj++) {
                int j = lane + jj * 32;
                if (j < HWSZ) {
                    float s = hsum2(acc2[rr][jj]) * 0.125f
                            + rb[rr * 28 + j / 14]
                            + rb[rr * 28 + 14 + j % 14];
                    vals[jj] = s;
                    m = fmaxf(m, s);
                }
            }
#pragma unroll
            for (int o = 16; o > 0; o >>= 1)
                m = fmaxf(m, __shfl_xor_sync(0xffffffffu, m, o));
            float lsum = 0.f;
#pragma unroll
            for (int jj = 0; jj < 7; jj++) {
                int j = lane + jj * 32;
                if (j < HWSZ) {
                    float e = __expf(vals[jj] - m);
                    pw[rr * 200 + j] = e;
                    lsum += e;
                }
            }
#pragma unroll
            for (int o = 16; o > 0; o >>= 1)
                lsum += __shfl_xor_sync(0xffffffffu, lsum, o);
            inv[rr] = 1.f / lsum;
        }
        __syncwarp();

        // P @ V: packed along key pairs (j, j+1); lane owns dims 2*lane, +1
        u64 o20[4] = {0ull, 0ull, 0ull, 0ull};
        u64 o21[4] = {0ull, 0ull, 0ull, 0ull};
#pragma unroll 2
        for (int j = 0; j < HWSZ; j += 2) {
            float2 va = *(const float2*)(vS + j * KSTR + 2 * lane);
            float2 vb = *(const float2*)(vS + (j + 1) * KSTR + 2 * lane);
            u64 vx = pack2(va.x, vb.x);
            u64 vy = pack2(va.y, vb.y);
#pragma unroll
            for (int rr = 0; rr < 4; rr++) {
                u64 pp = *(const u64*)(pw + rr * 200 + j);
                o20[rr] = fma2(pp, vx, o20[rr]);
                o21[rr] = fma2(pp, vy, o21[rr]);
            }
        }

        float* gout = g_att + ((size_t)b * HWSZ + r0) * CC + h * HDIM;
#pragma unroll
        for (int rr = 0; rr < 4; rr++) {
            float2 res;
            res.x = f2tf32(hsum2(o20[rr]) * inv[rr]);  // pre-round for proj GEMM
            res.y = f2tf32(hsum2(o21[rr]) * inv[rr]);
            *(float2*)(gout + rr * CC + 2 * lane) = res;
        }
        __syncwarp();
    }
}

// ---------------------------------------------------------------------------
extern "C" void kernel_launch(void* const* d_in, const int* in_sizes, int n_in,
                              void* d_out, int out_size)
{
    const float* x      = (const float*)d_in[0]; // (25088, 768)
    const float* w_qkv  = (const float*)d_in[1]; // (768, 2304)
    const float* b_qkv  = (const float*)d_in[2]; // (2304,)
    const float* rph    = (const float*)d_in[3]; // (27, 64)
    const float* rpw    = (const float*)d_in[4]; // (27, 64)
    const float* w_proj = (const float*)d_in[5]; // (768, 768)
    const float* b_proj = (const float*)d_in[6]; // (768,)
    float* out = (float*)d_out;                  // (25088, 768)

    float *d_x, *d_wqkv, *d_wproj;
    cudaGetSymbolAddress((void**)&d_x, g_x);
    cudaGetSymbolAddress((void**)&d_wqkv, g_wqkv);
    cudaGetSymbolAddress((void**)&d_wproj, g_wproj);

    cudaFuncSetAttribute(gemm_qkv_k,
                         cudaFuncAttributeMaxDynamicSharedMemorySize,
                         GEMM_SMEM_BYTES);
    cudaFuncSetAttribute(gemm_proj_k,
                         cudaFuncAttributeMaxDynamicSharedMemorySize,
                         GEMM_SMEM_BYTES);
    cudaFuncSetAttribute(attn_kernel,
                         cudaFuncAttributeMaxDynamicSharedMemorySize,
                         ATTN_SMEM_BYTES);

    // Pre-round GEMM inputs to tf32 (RN)
    {
        int n4 = MROWS * CC / 4;
        round_tf32_kernel<<<(n4 + 255) / 256, 256>>>(x, d_x, n4);
        n4 = CC * C3 / 4;
        round_tf32_kernel<<<(n4 + 255) / 256, 256>>>(w_qkv, d_wqkv, n4);
        n4 = CC * CC / 4;
        round_tf32_kernel<<<(n4 + 255) / 256, 256>>>(w_proj, d_wproj, n4);
    }

    dim3 g1(C3 / BN, MROWS / BM);   // 18 x 196
    gemm_qkv_k<<<g1, 256, GEMM_SMEM_BYTES>>>(b_qkv);

    attn_kernel<<<NHEADS_TOTAL, NTHR, ATTN_SMEM_BYTES>>>(rph, rpw);

    dim3 g2(CC / BN, MROWS / BM);   // 6 x 196
    gemm_proj_k<<<g2, 256, GEMM_SMEM_BYTES>>>(b_proj, out);
}

// round 8
// speedup vs baseline: 3.4815x; 1.9504x over previous
#include <cuda_runtime.h>
#include <cuda_fp16.h>
#include <mma.h>
#include <cstddef>
#include <cstdint>

using namespace nvcuda;

// Problem constants
#define BATCH 128
#define HH 14
#define WW 14
#define CC 768
#define NHEAD 12
#define HDIM 64
#define HWSZ 196          // 14*14
#define C3 2304           // 3*C
#define MROWS 25088       // BATCH*HWSZ
#define NHEADS_TOTAL 1536 // BATCH*NHEAD

typedef unsigned long long u64;

// Scratch buffers (device globals: no allocation allowed)
__device__ float  g_qkv[(size_t)MROWS * C3];  // qkv GEMM out (fp32)
__device__ __half g_att[(size_t)MROWS * CC];  // attention out (fp16)
__device__ __half g_x[(size_t)MROWS * CC];    // x (fp16)
__device__ __half g_wqkv[(size_t)CC * C3];    // w_qkv (fp16)
__device__ __half g_wproj[(size_t)CC * CC];   // w_proj (fp16)

// ---------------------------------------------------------------------------
// helpers
// ---------------------------------------------------------------------------
__global__ void to_half_kernel(const float* __restrict__ in,
                               __half* __restrict__ out, int n4)
{
    int i = blockIdx.x * blockDim.x + threadIdx.x;
    if (i < n4) {
        float4 v = ((const float4*)in)[i];
        __half2 a = __floats2half2_rn(v.x, v.y);
        __half2 b = __floats2half2_rn(v.z, v.w);
        uint2 pk;
        pk.x = *(uint32_t*)&a;
        pk.y = *(uint32_t*)&b;
        ((uint2*)out)[i] = pk;
    }
}

// packed f32x2 ops (Blackwell)
__device__ __forceinline__ u64 fma2(u64 a, u64 b, u64 c) {
    u64 d;
    asm("fma.rn.f32x2 %0, %1, %2, %3;" : "=l"(d) : "l"(a), "l"(b), "l"(c));
    return d;
}
__device__ __forceinline__ u64 pack2(float lo, float hi) {
    u64 d;
    asm("mov.b64 %0, {%1, %2};" : "=l"(d) : "f"(lo), "f"(hi));
    return d;
}
__device__ __forceinline__ float hsum2(u64 v) {
    float a, b;
    asm("mov.b64 {%0, %1}, %2;" : "=f"(a), "=f"(b) : "l"(v));
    return a + b;
}

__device__ __forceinline__ void cpa16(void* s, const void* g) {
    uint32_t sa = (uint32_t)__cvta_generic_to_shared(s);
    asm volatile("cp.async.cg.shared.global [%0], [%1], 16;\n" ::"r"(sa), "l"(g));
}
__device__ __forceinline__ void cpa_commit() {
    asm volatile("cp.async.commit_group;\n" ::);
}
template <int N>
__device__ __forceinline__ void cpa_wait() {
    asm volatile("cp.async.wait_group %0;\n" ::"n"(N));
}

// ---------------------------------------------------------------------------
// Pipelined fp16 GEMM: C(fp32) = A(MxK,f16) @ B(KxN,f16) + bias(fp32)
// BM=BN=128, BK=64, wmma m16n16k16, 2-stage cp.async, 256 thr, 2 CTA/SM.
// 8 warps in 2x4 layout, 64x32 output per warp.
// ---------------------------------------------------------------------------
#define BM 128
#define BN 128
#define BK 64
#define ASTR 40    // BK/... actually halves per A row: 64 + 8 pad? see below
#define BSTR 136   // halves per B row: 128 + 8 pad

// A tile rows are BK=64 halves + 8 pad = 72 halves
#define ASTRH 72

#define GEMM_SMEM_BYTES ((2 * BM * ASTRH + 2 * BK * BSTR) * 2 + 16 * BSTR * 4)

template <bool STORE_HALF>
__device__ __forceinline__ void gemm_body(
    const __half* __restrict__ A, const __half* __restrict__ Bm,
    const float* __restrict__ bias, void* __restrict__ Cout,
    int M, int N, int K)
{
    extern __shared__ char smraw[];
    __half* As = (__half*)smraw;                       // 2 x BM x ASTRH
    __half* Bs = As + 2 * BM * ASTRH;                  // 2 x BK x BSTR
    float* biasT = (float*)(Bs + 2 * BK * BSTR);       // 16 x BSTR fp32

    const int tid = threadIdx.x;
    const int m0 = blockIdx.y * BM;
    const int n0 = blockIdx.x * BN;

    for (int i = tid; i < 16 * BN; i += 256) {
        int rr = i >> 7, cc = i & 127;
        biasT[rr * BSTR + cc] = bias[n0 + cc];
    }
    __syncthreads();

    const int w  = tid >> 5;
    const int wm = w >> 2;   // 0..1
    const int wn = w & 3;    // 0..3

    wmma::fragment<wmma::accumulator, 16, 16, 16, float> acc[4][2];
#pragma unroll
    for (int i = 0; i < 4; i++)
#pragma unroll
        for (int j = 0; j < 2; j++)
            wmma::load_matrix_sync(acc[i][j], &biasT[wn * 32 + j * 16], BSTR,
                                   wmma::mem_row_major);

    // Staging: A tile 128 x 64 halves (128B/row = 8 x 16B), 256 thr -> 4 iters
    const int arow = tid >> 3, ac8 = (tid & 7) * 8;   // 32 rows per pass
    // B tile 64 x 128 halves (256B/row = 16 x 16B), 256 thr -> 4 iters
    const int brow = tid >> 4, bc8 = (tid & 15) * 8;  // 16 rows per pass

    const int T = K / BK;

    {
        const __half* ag = &A[(size_t)(m0 + arow) * K + ac8];
        const __half* bg = &Bm[(size_t)brow * N + n0 + bc8];
#pragma unroll
        for (int p = 0; p < 4; p++)
            cpa16(&As[(arow + p * 32) * ASTRH + ac8], ag + (size_t)(p * 32) * K);
#pragma unroll
        for (int p = 0; p < 4; p++)
            cpa16(&Bs[(brow + p * 16) * BSTR + bc8], bg + (size_t)(p * 16) * N);
        cpa_commit();
    }

    for (int t = 0; t < T; t++) {
        if (t + 1 < T) {
            const int st = (t + 1) & 1;
            const int kt = (t + 1) * BK;
            const __half* ag = &A[(size_t)(m0 + arow) * K + kt + ac8];
            const __half* bg = &Bm[(size_t)(kt + brow) * N + n0 + bc8];
            __half* asd = &As[st * BM * ASTRH];
            __half* bsd = &Bs[st * BK * BSTR];
#pragma unroll
            for (int p = 0; p < 4; p++)
                cpa16(&asd[(arow + p * 32) * ASTRH + ac8], ag + (size_t)(p * 32) * K);
#pragma unroll
            for (int p = 0; p < 4; p++)
                cpa16(&bsd[(brow + p * 16) * BSTR + bc8], bg + (size_t)(p * 16) * N);
            cpa_commit();
            cpa_wait<1>();
        } else {
            cpa_wait<0>();
        }
        __syncthreads();

        const __half* asrc = &As[(t & 1) * BM * ASTRH];
        const __half* bsrc = &Bs[(t & 1) * BK * BSTR];

#pragma unroll
        for (int kk = 0; kk < BK; kk += 16) {
            wmma::fragment<wmma::matrix_a, 16, 16, 16, __half, wmma::row_major> af[4];
            wmma::fragment<wmma::matrix_b, 16, 16, 16, __half, wmma::row_major> bf[2];
#pragma unroll
            for (int i = 0; i < 4; i++)
                wmma::load_matrix_sync(af[i], &asrc[(wm * 64 + i * 16) * ASTRH + kk], ASTRH);
#pragma unroll
            for (int j = 0; j < 2; j++)
                wmma::load_matrix_sync(bf[j], &bsrc[kk * BSTR + wn * 32 + j * 16], BSTR);
#pragma unroll
            for (int i = 0; i < 4; i++)
#pragma unroll
                for (int j = 0; j < 2; j++)
                    wmma::mma_sync(acc[i][j], af[i], bf[j], acc[i][j]);
        }
        __syncthreads();
    }

    if (STORE_HALF) {
        // not used (both GEMMs store fp32 here)
    }
#pragma unroll
    for (int i = 0; i < 4; i++)
#pragma unroll
        for (int j = 0; j < 2; j++)
            wmma::store_matrix_sync(
                (float*)Cout + (size_t)(m0 + wm * 64 + i * 16) * N + n0 + wn * 32 + j * 16,
                acc[i][j], N, wmma::mem_row_major);
}

__global__ __launch_bounds__(256, 2) void gemm_qkv_k(const float* __restrict__ bias)
{
    gemm_body<false>(g_x, g_wqkv, bias, g_qkv, MROWS, C3, CC);
}

__global__ __launch_bounds__(256, 2) void gemm_proj_k(
    const float* __restrict__ bias, float* __restrict__ C)
{
    gemm_body<false>(g_att, g_wproj, bias, C, MROWS, CC, CC);
}

// ---------------------------------------------------------------------------
// Fused attention, packed f32x2 FMA, 512 threads (16 warps) per CTA.
// One CTA per (batch, head). Output stored fp16 for the proj GEMM.
// ---------------------------------------------------------------------------
#define KSTR 68
#define NWARP 16
#define NTHR (NWARP * 32)

#define SM_K   (224 * KSTR)
#define SM_V   (196 * KSTR)
#define SM_RH  (27 * KSTR)
#define SM_RW  (27 * KSTR)
#define SM_Q   (NWARP * 4 * KSTR)
#define SM_P   (NWARP * 4 * 200)
#define SM_REL (NWARP * 4 * 28)
#define ATTN_SMEM_FLOATS (SM_K + SM_V + SM_RH + SM_RW + SM_Q + SM_P + SM_REL)
#define ATTN_SMEM_BYTES (ATTN_SMEM_FLOATS * 4)

__global__ __launch_bounds__(NTHR) void attn_kernel(
    const float* __restrict__ rph, const float* __restrict__ rpw)
{
    extern __shared__ float sm[];
    float* kS  = sm;
    float* vS  = kS + SM_K;
    float* RhS = vS + SM_V;
    float* RwS = RhS + SM_RH;
    float* qsm = RwS + SM_RW;
    float* pbf = qsm + SM_Q;
    float* rlb = pbf + SM_P;

    const int tid  = threadIdx.x;
    const int head = blockIdx.x;
    const int b = head / NHEAD;
    const int h = head % NHEAD;

    const float* gbase = g_qkv + (size_t)b * HWSZ * C3 + h * HDIM;

    for (int i = tid; i < HWSZ * HDIM; i += NTHR) {
        int j = i >> 6, d = i & 63;
        const float* p = gbase + (size_t)j * C3 + d;
        kS[j * KSTR + d] = p[768];
        vS[j * KSTR + d] = p[1536];
    }
    for (int i = tid; i < 28 * KSTR; i += NTHR) kS[196 * KSTR + i] = 0.f;
    for (int i = tid; i < 27 * HDIM; i += NTHR) {
        int r = i >> 6, d = i & 63;
        RhS[r * KSTR + d] = rph[i];
        RwS[r * KSTR + d] = rpw[i];
    }
    __syncthreads();

    const int wid = tid >> 5, lane = tid & 31;
    float* qw = qsm + wid * 4 * KSTR;
    float* pw = pbf + wid * 800;
    float* rb = rlb + wid * 112;

    for (int g = wid; g < 49; g += NWARP) {
        const int r0 = g * 4;

        for (int i = lane; i < 4 * HDIM; i += 32) {
            int rr = i >> 6, d = i & 63;
            qw[rr * KSTR + d] = gbase[(size_t)(r0 + rr) * C3 + d];
        }
        __syncwarp();

        // rel-pos dots (packed along d)
        for (int t = lane; t < 112; t += 32) {
            int rr = t / 28, wch = t % 28;
            int r = r0 + rr;
            const float* tab;
            int row;
            if (wch < 14) { row = r / 14 - wch + 13;        tab = RhS; }
            else          { row = r % 14 - (wch - 14) + 13; tab = RwS; }
            const u64* qp = (const u64*)(qw + rr * KSTR);
            const u64* tp = (const u64*)(tab + row * KSTR);
            u64 s2 = 0ull;
#pragma unroll
            for (int d = 0; d < 32; d++) s2 = fma2(qp[d], tp[d], s2);
            rb[rr * 28 + wch] = hsum2(s2);
        }
        __syncwarp();

        // QK^T: packed along d
        u64 acc2[4][7];
#pragma unroll
        for (int rr = 0; rr < 4; rr++)
#pragma unroll
            for (int jj = 0; jj < 7; jj++) acc2[rr][jj] = 0ull;

#pragma unroll 4
        for (int d0 = 0; d0 < 64; d0 += 4) {
            ulonglong2 qv[4];
#pragma unroll
            for (int rr = 0; rr < 4; rr++)
                qv[rr] = *(const ulonglong2*)(qw + rr * KSTR + d0);
#pragma unroll
            for (int jj = 0; jj < 7; jj++) {
                int j = lane + jj * 32;  // pad rows (>=196) are zero
                ulonglong2 kv = *(const ulonglong2*)(kS + j * KSTR + d0);
#pragma unroll
                for (int rr = 0; rr < 4; rr++) {
                    acc2[rr][jj] = fma2(kv.x, qv[rr].x, acc2[rr][jj]);
                    acc2[rr][jj] = fma2(kv.y, qv[rr].y, acc2[rr][jj]);
                }
            }
        }

        // softmax (scale 1/8, + rel bias)
        float inv[4];
#pragma unroll
        for (int rr = 0; rr < 4; rr++) {
            float vals[7];
            float m = -1e30f;
#pragma unroll
            for (int jj = 0; jj < 7; jj++) {
                int j = lane + jj * 32;
                if (j < HWSZ) {
                    float s = hsum2(acc2[rr][jj]) * 0.125f
                            + rb[rr * 28 + j / 14]
                            + rb[rr * 28 + 14 + j % 14];
                    vals[jj] = s;
                    m = fmaxf(m, s);
                }
            }
#pragma unroll
            for (int o = 16; o > 0; o >>= 1)
                m = fmaxf(m, __shfl_xor_sync(0xffffffffu, m, o));
            float lsum = 0.f;
#pragma unroll
            for (int jj = 0; jj < 7; jj++) {
                int j = lane + jj * 32;
                if (j < HWSZ) {
                    float e = __expf(vals[jj] - m);
                    pw[rr * 200 + j] = e;
                    lsum += e;
                }
            }
#pragma unroll
            for (int o = 16; o > 0; o >>= 1)
                lsum += __shfl_xor_sync(0xffffffffu, lsum, o);
            inv[rr] = 1.f / lsum;
        }
        __syncwarp();

        // P @ V: packed along key pairs
        u64 o20[4] = {0ull, 0ull, 0ull, 0ull};
        u64 o21[4] = {0ull, 0ull, 0ull, 0ull};
#pragma unroll 2
        for (int j = 0; j < HWSZ; j += 2) {
            float2 va = *(const float2*)(vS + j * KSTR + 2 * lane);
            float2 vb = *(const float2*)(vS + (j + 1) * KSTR + 2 * lane);
            u64 vx = pack2(va.x, vb.x);
            u64 vy = pack2(va.y, vb.y);
#pragma unroll
            for (int rr = 0; rr < 4; rr++) {
                u64 pp = *(const u64*)(pw + rr * 200 + j);
                o20[rr] = fma2(pp, vx, o20[rr]);
                o21[rr] = fma2(pp, vy, o21[rr]);
            }
        }

        __half* gout = g_att + ((size_t)b * HWSZ + r0) * CC + h * HDIM;
#pragma unroll
        for (int rr = 0; rr < 4; rr++) {
            __half2 res = __floats2half2_rn(hsum2(o20[rr]) * inv[rr],
                                            hsum2(o21[rr]) * inv[rr]);
            *(__half2*)(gout + (size_t)rr * CC + 2 * lane) = res;
        }
        __syncwarp();
    }
}

// ---------------------------------------------------------------------------
extern "C" void kernel_launch(void* const* d_in, const int* in_sizes, int n_in,
                              void* d_out, int out_size)
{
    const float* x      = (const float*)d_in[0]; // (25088, 768)
    const float* w_qkv  = (const float*)d_in[1]; // (768, 2304)
    const float* b_qkv  = (const float*)d_in[2]; // (2304,)
    const float* rph    = (const float*)d_in[3]; // (27, 64)
    const float* rpw    = (const float*)d_in[4]; // (27, 64)
    const float* w_proj = (const float*)d_in[5]; // (768, 768)
    const float* b_proj = (const float*)d_in[6]; // (768,)
    float* out = (float*)d_out;                  // (25088, 768)

    __half *d_x, *d_wqkv, *d_wproj;
    cudaGetSymbolAddress((void**)&d_x, g_x);
    cudaGetSymbolAddress((void**)&d_wqkv, g_wqkv);
    cudaGetSymbolAddress((void**)&d_wproj, g_wproj);

    cudaFuncSetAttribute(gemm_qkv_k,
                         cudaFuncAttributeMaxDynamicSharedMemorySize,
                         GEMM_SMEM_BYTES);
    cudaFuncSetAttribute(gemm_proj_k,
                         cudaFuncAttributeMaxDynamicSharedMemorySize,
                         GEMM_SMEM_BYTES);
    cudaFuncSetAttribute(attn_kernel,
                         cudaFuncAttributeMaxDynamicSharedMemorySize,
                         ATTN_SMEM_BYTES);

    // Convert GEMM inputs to fp16
    {
        int n4 = MROWS * CC / 4;
        to_half_kernel<<<(n4 + 255) / 256, 256>>>(x, d_x, n4);
        n4 = CC * C3 / 4;
        to_half_kernel<<<(n4 + 255) / 256, 256>>>(w_qkv, d_wqkv, n4);
        n4 = CC * CC / 4;
        to_half_kernel<<<(n4 + 255) / 256, 256>>>(w_proj, d_wproj, n4);
    }

    dim3 g1(C3 / BN, MROWS / BM);   // 18 x 196
    gemm_qkv_k<<<g1, 256, GEMM_SMEM_BYTES>>>(b_qkv);

    attn_kernel<<<NHEADS_TOTAL, NTHR, ATTN_SMEM_BYTES>>>(rph, rpw);

    dim3 g2(CC / BN, MROWS / BM);   // 6 x 196
    gemm_proj_k<<<g2, 256, GEMM_SMEM_BYTES>>>(b_proj, out);
}